// round 11
// baseline (speedup 1.0000x reference)
#include <cuda_runtime.h>

// DenseTNT postprocess: per-batch greedy NMS over 4096 goal candidates.
// k-th pick = argmax score among candidates not suppressed (d2 < 4.0) by
// already-picked goals. Key = (ordered_float(score) << 32) | (~idx) encodes
// stable-sort tie-break (equal score -> lower original index).
//
// R10 structure (lazy suppression + register-buffered overlapped gather) at
// TPB=256: 8-warp barriers (smaller arrival spread), 8-partial merge,
// PER=16 candidates/thread (extra cost only in the one-time initial scan;
// the lazy per-round common path is O(1) in PER).

#define B_       128
#define N_       4096
#define MODES_   6
#define THRESH2_ 4.0f
#define TPB_     256
#define PER_     16          // candidates per thread (contiguous chunk)
#define NW_      (TPB_ / 32) // 8 warps

typedef unsigned long long u64;

__global__ __launch_bounds__(TPB_, 1)
void densetnt_nms_kernel(const float* __restrict__ scores,   // [B, N]
                         const float* __restrict__ trajs,    // [B, 60, N]
                         const float* __restrict__ goals,    // [B, 2, N]
                         float* __restrict__ out)            // [B,6,30,2] ++ [B,6]
{
    const int b    = blockIdx.x;
    const int t    = threadIdx.x;
    const int w    = t >> 5;
    const int lane = t & 31;

    __shared__ float2 sgoal[N_];          // 32 KB goal mirror (broadcast reads)
    __shared__ u64    red[2][NW_];        // parity double-buffer
    __shared__ u64    win_s[MODES_];

    const float* sc = scores + (size_t)b * N_     + (size_t)t * PER_;
    const float* gx = goals  + (size_t)b * 2 * N_ + (size_t)t * PER_;
    const float* gy = gx + N_;
    const float* tb = trajs + (size_t)b * 60 * N_;
    float* ob = out + (size_t)b * MODES_ * 60;

    // Vectorized load of this thread's contiguous 16-candidate chunk.
    float x[PER_], y[PER_], sv[PER_];
#pragma unroll
    for (int q = 0; q < PER_ / 4; q++) {
        float4 a = ((const float4*)gx)[q];
        float4 c = ((const float4*)gy)[q];
        float4 s = ((const float4*)sc)[q];
        x[q*4+0]=a.x; x[q*4+1]=a.y; x[q*4+2]=a.z; x[q*4+3]=a.w;
        y[q*4+0]=c.x; y[q*4+1]=c.y; y[q*4+2]=c.z; y[q*4+3]=c.w;
        sv[q*4+0]=s.x; sv[q*4+1]=s.y; sv[q*4+2]=s.z; sv[q*4+3]=s.w;
    }

    // Fill goal mirror with 8 STS.128.
    {
        float4* dst = (float4*)(sgoal + (size_t)t * PER_);
#pragma unroll
        for (int q = 0; q < PER_ / 2; q++)
            dst[q] = make_float4(x[q*2], y[q*2], x[q*2+1], y[q*2+1]);
    }

    u64 key[PER_];
#pragma unroll
    for (int j = 0; j < PER_; j++) {
        unsigned i  = (unsigned)(t * PER_ + j);
        unsigned u  = __float_as_uint(sv[j]);
        unsigned os = u ^ (0x80000000u | (unsigned)(((int)u) >> 31)); // order-preserving
        key[j] = ((u64)os << 32) | (u64)(0xFFFFFFFFu - i);
    }

    // Initial local best (no picks yet -> no validation needed).
    u64 bk = key[0]; float bx = x[0], by = y[0];
#pragma unroll
    for (int j = 1; j < PER_; j++)
        if (key[j] > bk) { bk = key[j]; bx = x[j]; by = y[j]; }

    float px[MODES_], py[MODES_];   // pick history (static-indexed -> registers)
    float gbuf[MODES_];             // gather buffer (gather threads only)
    unsigned wmask = 0;             // bit m set <=> round m had a winner

    const bool is_gather = (t >= TPB_ - 64) && (t - (TPB_ - 64) < 60);
    const int  ge        = t - (TPB_ - 64);   // gather element (valid if is_gather)

    __syncthreads();   // sgoal ready

#pragma unroll
    for (int m = 0; m < MODES_; m++) {
        // --- warp max over the 32 lazy local-bests (5 shfl levels) ---
        u64 best = bk;
#pragma unroll
        for (int o = 16; o > 0; o >>= 1) {
            u64 v = __shfl_xor_sync(0xFFFFFFFFu, best, o);
            best = v > best ? v : best;
        }
        if (lane == 0) red[m & 1][w] = best;
        __syncthreads();   // ONLY barrier this round (8 warps)

        // --- all threads merge the 8 warp partials (4x LDS.128) ---
        const ulonglong2* rp = (const ulonglong2*)red[m & 1];
        u64 win = 0ull;
#pragma unroll
        for (int q = 0; q < NW_ / 2; q++) {
            ulonglong2 p = rp[q];
            u64 hi = p.x > p.y ? p.x : p.y;
            win = hi > win ? hi : win;
        }
        if (t == 0) win_s[m] = win;

        if (win != 0ull) {
            wmask |= 1u << m;
            const int widx = (int)(0xFFFFFFFFu - (unsigned)(win & 0xFFFFFFFFull));
            const float2 g = sgoal[widx];      // broadcast read
            px[m] = g.x; py[m] = g.y;

            // --- gather: ISSUE ONLY (value consumed after the loop) ---
            if (is_gather) gbuf[m] = __ldg(tb + (size_t)ge * N_ + widx);

            // --- lazy update of local best (skipped after the final pick) ---
            if (m < MODES_ - 1) {
                float dx = bx - g.x, dy = by - g.y;
                bool need = (bk == win) | (bk != 0ull && dx * dx + dy * dy < THRESH2_);
                if (need) {
#pragma unroll
                    for (int j = 0; j < PER_; j++) key[j] = (key[j] == bk) ? 0ull : key[j];
                    for (;;) {   // rare path: recompute + validate vs pick history
                        u64 nk = key[0]; float nx = x[0], ny = y[0];
#pragma unroll
                        for (int j = 1; j < PER_; j++)
                            if (key[j] > nk) { nk = key[j]; nx = x[j]; ny = y[j]; }
                        if (nk == 0ull) { bk = 0ull; break; }
                        bool sup = false;
#pragma unroll
                        for (int r = 0; r < MODES_; r++) {
                            if (r <= m) {
                                float ddx = nx - px[r], ddy = ny - py[r];
                                sup |= (ddx * ddx + ddy * ddy < THRESH2_);
                            }
                        }
                        if (sup) {
#pragma unroll
                            for (int j = 0; j < PER_; j++) key[j] = (key[j] == nk) ? 0ull : key[j];
                        } else { bk = nk; bx = nx; by = ny; break; }
                    }
                }
            }
        }
        // no trailing barrier: next round writes the other parity buffer; the
        // round-(m+1) barrier bounds warp skew to one round.
    }

    // --- gather epilogue: 6 STGs per gather thread; fallback modes reuse
    //     round-0's value (round 0 always has a winner: all keys nonzero) ---
    if (is_gather) {
#pragma unroll
        for (int m = 0; m < MODES_; m++) {
            ob[m * 60 + ge] = (wmask & (1u << m)) ? gbuf[m] : gbuf[0];
        }
    }

    __syncthreads();   // win_s[] complete

    // scores (empty slot -> round-0 winner = global top-1)
    if (t < MODES_) {
        u64 wv = win_s[t];
        if (wv == 0ull) wv = win_s[0];
        unsigned os = (unsigned)(wv >> 32);
        out[(size_t)B_ * MODES_ * 60 + (size_t)b * MODES_ + t] =
            __uint_as_float(os ^ (0x80000000u | (unsigned)(((int)~os) >> 31)));
    }
}

extern "C" void kernel_launch(void* const* d_in, const int* in_sizes, int n_in,
                              void* d_out, int out_size)
{
    const float* goals_scores = (const float*)d_in[0];  // [128, 4096]
    const float* traj_preds   = (const float*)d_in[1];  // [128, 60, 4096]
    const float* pred_goals   = (const float*)d_in[2];  // [128, 2, 4096]
    float* out = (float*)d_out;

    densetnt_nms_kernel<<<B_, TPB_>>>(goals_scores, traj_preds, pred_goals, out);
}